// round 8
// baseline (speedup 1.0000x reference)
#include <cuda_runtime.h>
#include <cuda_bf16.h>
#include <math.h>
#include <stdint.h>

#define NN   20000
#define FF   3000
#define KP1  3072          // FF padded to multiple of 32
#define ZD   128
#define H1D  512
#define G1D  32
#define OUTD 3

// ---------------- scratch (allocation-free) ----------------
__device__ unsigned short g_xhi [NN * KP1];
__device__ unsigned short g_xlo [NN * KP1];
__device__ unsigned short g_w1hi[H1D * KP1];
__device__ unsigned short g_w1lo[H1D * KP1];
__device__ unsigned short g_w2hi[ZD * H1D];
__device__ unsigned short g_w2lo[ZD * H1D];
__device__ unsigned short g_f1hi[NN * H1D];
__device__ unsigned short g_f1lo[NN * H1D];
__device__ float g_fe [NN * ZD];
__device__ float g_deg [NN];
__device__ float g_dinv[NN];
__device__ float g_h   [NN * G1D];
__device__ float g_agg1[NN * G1D];
__device__ float g_h1  [NN * G1D];
__device__ float g_hm  [NN * OUTD];
__device__ float g_hl  [NN * OUTD];
__device__ float g_aggm[NN * OUTD];
__device__ float g_aggl[NN * OUTD];

// ================= PTX helpers (base-target safe) =================
__device__ __forceinline__ uint32_t smem_u32(const void* p) {
    uint32_t a;
    asm("{ .reg .u64 t; cvta.to.shared.u64 t, %1; cvt.u32.u64 %0, t; }" : "=r"(a) : "l"(p));
    return a;
}
__device__ __forceinline__ void ldsm4(uint32_t* r, uint32_t a) {
    asm volatile("ldmatrix.sync.aligned.m8n8.x4.shared.b16 {%0,%1,%2,%3}, [%4];"
                 : "=r"(r[0]), "=r"(r[1]), "=r"(r[2]), "=r"(r[3]) : "r"(a));
}
__device__ __forceinline__ void mma16816(float* d, const uint32_t* a, const uint32_t* b) {
    asm volatile(
        "mma.sync.aligned.m16n8k16.row.col.f32.bf16.bf16.f32 "
        "{%0,%1,%2,%3}, {%4,%5,%6,%7}, {%8,%9}, {%0,%1,%2,%3};"
        : "+f"(d[0]), "+f"(d[1]), "+f"(d[2]), "+f"(d[3])
        : "r"(a[0]), "r"(a[1]), "r"(a[2]), "r"(a[3]), "r"(b[0]), "r"(b[1]));
}
__device__ __forceinline__ void cpa16(uint32_t dst, const void* src, int sz) {
    asm volatile("cp.async.cg.shared.global [%0], [%1], 16, %2;"
                 :: "r"(dst), "l"(src), "r"(sz) : "memory");
}
#define CP_COMMIT() asm volatile("cp.async.commit_group;" ::: "memory")
#define CP_WAIT1()  asm volatile("cp.async.wait_group 1;" ::: "memory")

__device__ __forceinline__ void split1(float v, unsigned short& h, unsigned short& l) {
    __nv_bfloat16 hb = __float2bfloat16(v);
    __nv_bfloat16 lb = __float2bfloat16(v - __bfloat162float(hb));
    h = __bfloat16_as_ushort(hb);
    l = __bfloat16_as_ushort(lb);
}

// ================= pre-split bf16 HMMA GEMM (R5 structure) =================
// C[M,Ntot] = relu(A@B^T + bias); A,B pre-split bf16 hi/lo, K padded.
// 3 passes: hi*hi + hi*lo + lo*hi, fp32 accumulators.
// 2-stage cp.async ring, 2 CTAs/SM; B fragments via ldsm4.
template <int BF16OUT>
__global__ void __launch_bounds__(256, 2)
mma_gemm(const unsigned short* __restrict__ Ahi, const unsigned short* __restrict__ Alo,
         const unsigned short* __restrict__ Bhi, const unsigned short* __restrict__ Blo,
         const float* __restrict__ bias, float* __restrict__ Cf,
         unsigned short* __restrict__ Chi, unsigned short* __restrict__ Clo,
         int M, int Kp, int Ntot) {
    constexpr int BM = 128, BN = 128, BK = 32;
    constexpr int LDB = 80;                 // 64B data + 16B pad (LDSM conflict-free)
    constexpr int TILE = BM * LDB;          // 10240
    constexpr int STAGE = 4 * TILE;         // Ahi,Alo,Bhi,Blo

    extern __shared__ char sm[];
    const int tid = threadIdx.x, lane = tid & 31, wid = tid >> 5;
    const int bm = blockIdx.y * BM, bn = blockIdx.x * BN;
    const int wm = (wid >> 2) * 64, wn = (wid & 3) * 32;
    const uint32_t sb = smem_u32(sm);
    const int nk = Kp / BK;

    const int lr = tid >> 2;
    const int lcB = (tid & 3) * 16;
    const int lcE = (tid & 3) * 8;

    auto load_stage = [&](int i, int s) {
        const long k0 = (long)i * BK;
        const uint32_t base = sb + s * STAGE;
#pragma unroll
        for (int rep = 0; rep < 2; rep++) {
            const int r = lr + rep * 64;
            const uint32_t doff = (uint32_t)(r * LDB) + lcB;
            const int arow = (bm + r < M) ? (bm + r) : (M - 1);
            const int aok = (bm + r < M) ? 16 : 0;
            const long aoff = (long)arow * Kp + k0 + lcE;
            const long boff = (long)(bn + r) * Kp + k0 + lcE;
            cpa16(base + doff,            Ahi + aoff, aok);
            cpa16(base + TILE + doff,     Alo + aoff, aok);
            cpa16(base + 2 * TILE + doff, Bhi + boff, 16);
            cpa16(base + 3 * TILE + doff, Blo + boff, 16);
        }
        CP_COMMIT();
    };

    float acc[4][4][4];
#pragma unroll
    for (int i = 0; i < 4; i++)
#pragma unroll
        for (int j = 0; j < 4; j++)
#pragma unroll
            for (int v = 0; v < 4; v++) acc[i][j][v] = 0.f;

    // ldmatrix lane mappings (both validated bit-exact in prior rounds)
    const int a_row  = (lane & 7) + ((lane >> 3) & 1) * 8;
    const int a_kadd = (lane >> 4) * 8;
    const int b_row  = (lane & 7) + ((lane >> 4) & 1) * 8;  // x4 B-pair mapping
    const int b_kadd = ((lane >> 3) & 1) * 8;

    load_stage(0, 0);
    load_stage(1, 1);

#pragma unroll 1
    for (int i = 0; i < nk; i++) {
        const int cur = i & 1;
        CP_WAIT1();
        __syncthreads();

        const uint32_t abase = sb + cur * STAGE;
        const uint32_t bbase = abase + 2 * TILE;
#pragma unroll
        for (int ks = 0; ks < 2; ks++) {
            const int k16 = ks * 16;
            uint32_t ahi[4][4], alo[4][4], bhi[2][4], blo[2][4];
#pragma unroll
            for (int mi = 0; mi < 4; mi++) {
                uint32_t ad = abase + (uint32_t)((wm + mi * 16 + a_row) * LDB + (k16 + a_kadd) * 2);
                ldsm4(ahi[mi], ad);
                ldsm4(alo[mi], ad + TILE);
            }
#pragma unroll
            for (int np = 0; np < 2; np++) {
                uint32_t bd = bbase + (uint32_t)((wn + np * 16 + b_row) * LDB + (k16 + b_kadd) * 2);
                ldsm4(bhi[np], bd);
                ldsm4(blo[np], bd + TILE);
            }
#pragma unroll
            for (int mi = 0; mi < 4; mi++)
#pragma unroll
                for (int ni = 0; ni < 4; ni++)
                    mma16816(acc[mi][ni], ahi[mi], &bhi[ni >> 1][(ni & 1) * 2]);
#pragma unroll
            for (int mi = 0; mi < 4; mi++)
#pragma unroll
                for (int ni = 0; ni < 4; ni++)
                    mma16816(acc[mi][ni], ahi[mi], &blo[ni >> 1][(ni & 1) * 2]);
#pragma unroll
            for (int mi = 0; mi < 4; mi++)
#pragma unroll
                for (int ni = 0; ni < 4; ni++)
                    mma16816(acc[mi][ni], alo[mi], &bhi[ni >> 1][(ni & 1) * 2]);
        }
        __syncthreads();
        if (i + 2 < nk) load_stage(i + 2, cur);
    }

    // epilogue: bias + relu; fp32 out or bf16 hi/lo split out
#pragma unroll
    for (int mi = 0; mi < 4; mi++) {
#pragma unroll
        for (int ni = 0; ni < 4; ni++) {
            const int col = bn + wn + ni * 8 + (lane & 3) * 2;
            const float b0 = bias[col], b1 = bias[col + 1];
#pragma unroll
            for (int half = 0; half < 2; half++) {
                const int r = bm + wm + mi * 16 + (lane >> 2) + half * 8;
                if (r >= M) continue;
                float v0 = fmaxf(acc[mi][ni][half * 2 + 0] + b0, 0.f);
                float v1 = fmaxf(acc[mi][ni][half * 2 + 1] + b1, 0.f);
                if (BF16OUT) {
                    unsigned short h0, l0, h1, l1;
                    split1(v0, h0, l0);
                    split1(v1, h1, l1);
                    *(uint32_t*)(Chi + (long)r * Ntot + col) = (uint32_t)h0 | ((uint32_t)h1 << 16);
                    *(uint32_t*)(Clo + (long)r * Ntot + col) = (uint32_t)l0 | ((uint32_t)l1 << 16);
                } else {
                    float2 o = make_float2(v0, v1);
                    *(float2*)(Cf + (long)r * Ntot + col) = o;
                }
            }
        }
    }
}

// ---------------- split x: fp32 [M,K] -> bf16 hi/lo [M,Kp] ----------------
__global__ void split_pad(const float* __restrict__ in, unsigned short* __restrict__ hi,
                          unsigned short* __restrict__ lo, int M, int K, int Kp) {
    long idx = (long)blockIdx.x * blockDim.x + threadIdx.x;
    long tot = (long)M * (Kp / 4);
    if (idx >= tot) return;
    int r = (int)(idx / (Kp / 4));
    int c = (int)(idx % (Kp / 4)) * 4;
    float4 v = make_float4(0.f, 0.f, 0.f, 0.f);
    if (c < K) v = *(const float4*)(in + (long)r * K + c);
    unsigned short h[4], l[4];
    split1(v.x, h[0], l[0]); split1(v.y, h[1], l[1]);
    split1(v.z, h[2], l[2]); split1(v.w, h[3], l[3]);
    *(ushort4*)(hi + (long)r * Kp + c) = make_ushort4(h[0], h[1], h[2], h[3]);
    *(ushort4*)(lo + (long)r * Kp + c) = make_ushort4(l[0], l[1], l[2], l[3]);
}

// ---------------- transpose + split: W[R,C] -> hi/lo[C,Rp] ----------------
__global__ void transpose_split(const float* __restrict__ in, unsigned short* __restrict__ hi,
                                unsigned short* __restrict__ lo, int R, int C, int Rp) {
    __shared__ float t[32][33];
    int c = blockIdx.x * 32 + threadIdx.x;
    int r = blockIdx.y * 32 + threadIdx.y;
#pragma unroll
    for (int i = 0; i < 32; i += 8)
        t[threadIdx.y + i][threadIdx.x] = (r + i < R && c < C) ? in[(long)(r + i) * C + c] : 0.f;
    __syncthreads();
    int oc  = blockIdx.y * 32 + threadIdx.x;
    int orr = blockIdx.x * 32 + threadIdx.y;
#pragma unroll
    for (int i = 0; i < 32; i += 8)
        if (orr + i < C && oc < Rp) {
            float v = t[threadIdx.x][threadIdx.y + i];
            unsigned short h, l;
            split1(v, h, l);
            hi[(long)(orr + i) * Rp + oc] = h;
            lo[(long)(orr + i) * Rp + oc] = l;
        }
}

// ---------------- small GEMM: h = fe(Nx128) @ W(128x32) ----------------
__global__ void gemm_z_g1(const float* __restrict__ A, const float* __restrict__ W,
                          float* __restrict__ C, int M) {
    __shared__ float Ws[ZD * G1D];
    __shared__ float Asm[8 * ZD];
    const int t = threadIdx.x;
    const int base = blockIdx.x * 8;
#pragma unroll
    for (int i = 0; i < 16; i++) Ws[t + i * 256] = W[t + i * 256];
#pragma unroll
    for (int i = 0; i < 4; i++) {
        int idx = t + i * 256;
        int r = idx >> 7, c = idx & 127;
        Asm[r * ZD + c] = (base + r < M) ? A[(long)(base + r) * ZD + c] : 0.f;
    }
    __syncthreads();
    int r = t >> 5, c = t & 31;
    if (base + r < M) {
        float s = 0.f;
#pragma unroll
        for (int k = 0; k < ZD; k++) s = fmaf(Asm[r * ZD + k], Ws[k * G1D + c], s);
        C[(long)(base + r) * G1D + c] = s;
    }
}

// ---------------- head GEMMs ----------------
__global__ void gemm_heads(const float* __restrict__ H, const float* __restrict__ W2,
                           const float* __restrict__ W3,
                           float* __restrict__ HM, float* __restrict__ HL, int M) {
    __shared__ float sh[256 * 33];
    __shared__ float W2s[G1D * OUTD], W3s[G1D * OUTD];
    const int t = threadIdx.x;
    const int base = blockIdx.x * 256;
    if (t < G1D * OUTD) { W2s[t] = W2[t]; W3s[t] = W3[t]; }
#pragma unroll
    for (int i = 0; i < 32; i++) {
        int idx = t + i * 256;
        int r = idx >> 5, c = idx & 31;
        sh[r * 33 + c] = (base + r < M) ? H[(long)(base + r) * G1D + c] : 0.f;
    }
    __syncthreads();
    int row = base + t;
    if (row < M) {
        float m0 = 0, m1 = 0, m2 = 0, l0 = 0, l1 = 0, l2 = 0;
#pragma unroll
        for (int k = 0; k < G1D; k++) {
            float v = sh[t * 33 + k];
            m0 = fmaf(v, W2s[k * 3 + 0], m0);
            m1 = fmaf(v, W2s[k * 3 + 1], m1);
            m2 = fmaf(v, W2s[k * 3 + 2], m2);
            l0 = fmaf(v, W3s[k * 3 + 0], l0);
            l1 = fmaf(v, W3s[k * 3 + 1], l1);
            l2 = fmaf(v, W3s[k * 3 + 2], l2);
        }
        HM[row * 3 + 0] = m0; HM[row * 3 + 1] = m1; HM[row * 3 + 2] = m2;
        HL[row * 3 + 0] = l0; HL[row * 3 + 1] = l1; HL[row * 3 + 2] = l2;
    }
}

// ---------------- graph helpers ----------------
__global__ void init_deg_kernel(float* deg, int n) {
    int i = blockIdx.x * blockDim.x + threadIdx.x;
    if (i < n) deg[i] = 1.0f;
}
__global__ void deg_kernel(const int* __restrict__ dst, float* deg, int E) {
    int e = blockIdx.x * blockDim.x + threadIdx.x;
    if (e < E) atomicAdd(&deg[dst[e]], 1.0f);
}
__global__ void dinv_kernel(const float* __restrict__ deg, float* dinv, int n) {
    int i = blockIdx.x * blockDim.x + threadIdx.x;
    if (i < n) dinv[i] = rsqrtf(deg[i]);
}
// 8 threads per edge, float4 per thread: index loads /4, LDG /4, REDs unchanged
__global__ void agg1_kernel(const int* __restrict__ src, const int* __restrict__ dst,
                            const float* __restrict__ dinv, const float* __restrict__ H,
                            float* __restrict__ AGG, int E) {
    long tid = (long)blockIdx.x * blockDim.x + threadIdx.x;
    if (tid >= (long)E * 8) return;
    int e = (int)(tid >> 3), j = (int)(tid & 7) * 4;
    int s = src[e], d = dst[e];
    float w = dinv[s] * dinv[d];
    float4 hv = *(const float4*)(H + (long)s * G1D + j);
    float* dstp = AGG + (long)d * G1D + j;
    atomicAdd(dstp + 0, hv.x * w);
    atomicAdd(dstp + 1, hv.y * w);
    atomicAdd(dstp + 2, hv.z * w);
    atomicAdd(dstp + 3, hv.w * w);
}
__global__ void h1_kernel(const float* __restrict__ AGG, const float* __restrict__ H,
                          const float* __restrict__ dinv, float* __restrict__ H1, int n) {
    long tid = (long)blockIdx.x * blockDim.x + threadIdx.x;
    if (tid >= (long)n * G1D) return;
    int i = (int)(tid >> 5);
    float w = dinv[i];
    H1[tid] = tanhf(AGG[tid] + H[tid] * w * w);
}
__global__ void agg2_kernel(const int* __restrict__ src, const int* __restrict__ dst,
                            const float* __restrict__ dinv,
                            const float* __restrict__ HM, const float* __restrict__ HL,
                            float* __restrict__ AM, float* __restrict__ AL, int E) {
    int e = blockIdx.x * blockDim.x + threadIdx.x;
    if (e >= E) return;
    int s = src[e], d = dst[e];
    float w = dinv[s] * dinv[d];
#pragma unroll
    for (int j = 0; j < OUTD; j++) {
        atomicAdd(&AM[d * OUTD + j], HM[s * OUTD + j] * w);
        atomicAdd(&AL[d * OUTD + j], HL[s * OUTD + j] * w);
    }
}
__global__ void fin_kernel(const float* __restrict__ AM, const float* __restrict__ AL,
                           const float* __restrict__ HM, const float* __restrict__ HL,
                           const float* __restrict__ dinv, float* __restrict__ out, int n) {
    int tid = blockIdx.x * blockDim.x + threadIdx.x;
    if (tid >= n * OUTD) return;
    int i = tid / OUTD;
    float w = dinv[i] * dinv[i];
    out[tid]            = AM[tid] + HM[tid] * w;
    out[n * OUTD + tid] = AL[tid] + HL[tid] * w;
}
__global__ void pe_kernel(const float* __restrict__ fe, const float* __restrict__ coords,
                          float* __restrict__ out, int n) {
    long tid = (long)blockIdx.x * blockDim.x + threadIdx.x;
    if (tid >= (long)n * ZD) return;
    int node = (int)(tid >> 7);
    int z = (int)(tid & 127);
    int c = z >> 6;
    int t = z & 63;
    int idx = (t < 32) ? t : t - 32;
    float fr = exp2f(6.0f * (1.0f - (float)idx * (1.0f / 31.0f)));
    float v = coords[node * 2 + c] * fr;
    float p = (t < 32) ? sinf(v) : cosf(v);
    out[tid] = fe[tid] + 0.1f * p;
}

// ---------------- launch ----------------
extern "C" void kernel_launch(void* const* d_in, const int* in_sizes, int n_in,
                              void* d_out, int out_size) {
    const float* x      = (const float*)d_in[0];
    const float* coords = (const float*)d_in[1];
    const float* W1     = (const float*)d_in[2];
    const float* b1     = (const float*)d_in[3];
    const float* W2     = (const float*)d_in[4];
    const float* b2     = (const float*)d_in[5];
    const float* Wg1    = (const float*)d_in[6];
    const float* Wg2    = (const float*)d_in[7];
    const float* Wg3    = (const float*)d_in[8];
    const int*   ei     = (const int*)d_in[9];
    const int E = in_sizes[9] / 2;
    const int* src = ei;
    const int* dst = ei + E;
    float* out = (float*)d_out;

    unsigned short *xhi, *xlo, *w1hi, *w1lo, *w2hi, *w2lo, *f1hi, *f1lo;
    float *fe, *deg, *dinv, *h, *agg1, *h1, *hm, *hl, *am, *al;
    cudaGetSymbolAddress((void**)&xhi,  g_xhi);
    cudaGetSymbolAddress((void**)&xlo,  g_xlo);
    cudaGetSymbolAddress((void**)&w1hi, g_w1hi);
    cudaGetSymbolAddress((void**)&w1lo, g_w1lo);
    cudaGetSymbolAddress((void**)&w2hi, g_w2hi);
    cudaGetSymbolAddress((void**)&w2lo, g_w2lo);
    cudaGetSymbolAddress((void**)&f1hi, g_f1hi);
    cudaGetSymbolAddress((void**)&f1lo, g_f1lo);
    cudaGetSymbolAddress((void**)&fe,   g_fe);
    cudaGetSymbolAddress((void**)&deg,  g_deg);
    cudaGetSymbolAddress((void**)&dinv, g_dinv);
    cudaGetSymbolAddress((void**)&h,    g_h);
    cudaGetSymbolAddress((void**)&agg1, g_agg1);
    cudaGetSymbolAddress((void**)&h1,   g_h1);
    cudaGetSymbolAddress((void**)&hm,   g_hm);
    cudaGetSymbolAddress((void**)&hl,   g_hl);
    cudaGetSymbolAddress((void**)&am,   g_aggm);
    cudaGetSymbolAddress((void**)&al,   g_aggl);

    constexpr int SMEM = 2 * 4 * 128 * 80;   // 81920 B (2-stage ring, 2 CTAs/SM)
    cudaFuncSetAttribute(mma_gemm<0>, cudaFuncAttributeMaxDynamicSharedMemorySize, SMEM);
    cudaFuncSetAttribute(mma_gemm<1>, cudaFuncAttributeMaxDynamicSharedMemorySize, SMEM);

    // launches 1-3: accumulator zeroing (graph replays)
    cudaMemsetAsync(agg1, 0, sizeof(float) * NN * G1D);
    cudaMemsetAsync(am,   0, sizeof(float) * NN * OUTD);
    cudaMemsetAsync(al,   0, sizeof(float) * NN * OUTD);

    // launches 4-6: operand pre-split
    split_pad<<<(int)(((long)NN * (KP1 / 4) + 255) / 256), 256>>>(x, xhi, xlo, NN, FF, KP1);
    {
        dim3 b(32, 8);
        transpose_split<<<dim3((H1D + 31) / 32, (KP1 + 31) / 32), b>>>(W1, w1hi, w1lo, FF, H1D, KP1);
        transpose_split<<<dim3((ZD + 31) / 32, (H1D + 31) / 32), b>>>(W2, w2hi, w2lo, H1D, ZD, H1D);
    }

    // launch 7 (ncu -s picks this one): big GEMM
    mma_gemm<1><<<dim3(H1D / 128, (NN + 127) / 128), 256, SMEM>>>(
        xhi, xlo, w1hi, w1lo, b1, nullptr, f1hi, f1lo, NN, KP1, H1D);
    mma_gemm<0><<<dim3(ZD / 128, (NN + 127) / 128), 256, SMEM>>>(
        f1hi, f1lo, w2hi, w2lo, b2, fe, nullptr, nullptr, NN, H1D, ZD);

    // positional embedding (mu | logstd | po_emb)
    pe_kernel<<<(int)(((long)NN * ZD + 255) / 256), 256>>>(fe, coords, out + 2 * NN * OUTD, NN);

    // GCN layer 1
    gemm_z_g1<<<(NN + 7) / 8, 256>>>(fe, Wg1, h, NN);
    init_deg_kernel<<<(NN + 255) / 256, 256>>>(deg, NN);
    deg_kernel<<<(E + 255) / 256, 256>>>(dst, deg, E);
    dinv_kernel<<<(NN + 255) / 256, 256>>>(deg, dinv, NN);
    agg1_kernel<<<(int)(((long)E * 8 + 255) / 256), 256>>>(src, dst, dinv, h, agg1, E);
    h1_kernel<<<(int)(((long)NN * G1D + 255) / 256), 256>>>(agg1, h, dinv, h1, NN);

    // heads
    gemm_heads<<<(NN + 255) / 256, 256>>>(h1, Wg2, Wg3, hm, hl, NN);
    agg2_kernel<<<(E + 255) / 256, 256>>>(src, dst, dinv, hm, hl, am, al, E);
    fin_kernel<<<(NN * OUTD + 255) / 256, 256>>>(am, al, hm, hl, dinv, out, NN);
}

// round 10
// speedup vs baseline: 1.5343x; 1.5343x over previous
#include <cuda_runtime.h>
#include <cuda_bf16.h>
#include <math.h>
#include <stdint.h>

#define NN   20000
#define FF   3000
#define KP1  3072          // FF padded to multiple of 32
#define ZD   128
#define H1D  512
#define G1D  32
#define OUTD 3

// ---------------- scratch (allocation-free) ----------------
__device__ unsigned short g_xhi [NN * KP1];
__device__ unsigned short g_xlo [NN * KP1];
__device__ unsigned short g_w1hi[H1D * KP1];
__device__ unsigned short g_w1lo[H1D * KP1];
__device__ unsigned short g_w2hi[ZD * H1D];
__device__ unsigned short g_w2lo[ZD * H1D];
__device__ unsigned short g_f1hi[NN * H1D];
__device__ unsigned short g_f1lo[NN * H1D];
__device__ float g_fe [NN * ZD];
__device__ float g_deg [NN];
__device__ float g_dinv[NN];
__device__ float g_h   [NN * G1D];
__device__ float g_agg1[NN * G1D];
__device__ float g_h1  [NN * G1D];
__device__ float g_hm  [NN * OUTD];
__device__ float g_hl  [NN * OUTD];
__device__ float g_aggm[NN * OUTD];
__device__ float g_aggl[NN * OUTD];

// ================= PTX helpers (base-target safe) =================
__device__ __forceinline__ uint32_t smem_u32(const void* p) {
    uint32_t a;
    asm("{ .reg .u64 t; cvta.to.shared.u64 t, %1; cvt.u32.u64 %0, t; }" : "=r"(a) : "l"(p));
    return a;
}
__device__ __forceinline__ void ldsm4(uint32_t* r, uint32_t a) {
    asm volatile("ldmatrix.sync.aligned.m8n8.x4.shared.b16 {%0,%1,%2,%3}, [%4];"
                 : "=r"(r[0]), "=r"(r[1]), "=r"(r[2]), "=r"(r[3]) : "r"(a));
}
__device__ __forceinline__ void ldsm2(uint32_t* r, uint32_t a) {
    asm volatile("ldmatrix.sync.aligned.m8n8.x2.shared.b16 {%0,%1}, [%2];"
                 : "=r"(r[0]), "=r"(r[1]) : "r"(a));
}
__device__ __forceinline__ void mma16816(float* d, const uint32_t* a, const uint32_t* b) {
    asm volatile(
        "mma.sync.aligned.m16n8k16.row.col.f32.bf16.bf16.f32 "
        "{%0,%1,%2,%3}, {%4,%5,%6,%7}, {%8,%9}, {%0,%1,%2,%3};"
        : "+f"(d[0]), "+f"(d[1]), "+f"(d[2]), "+f"(d[3])
        : "r"(a[0]), "r"(a[1]), "r"(a[2]), "r"(a[3]), "r"(b[0]), "r"(b[1]));
}
__device__ __forceinline__ void cpa16(uint32_t dst, const void* src, int sz) {
    asm volatile("cp.async.cg.shared.global [%0], [%1], 16, %2;"
                 :: "r"(dst), "l"(src), "r"(sz) : "memory");
}
#define CP_COMMIT() asm volatile("cp.async.commit_group;" ::: "memory")
#define CP_WAIT1()  asm volatile("cp.async.wait_group 1;" ::: "memory")

__device__ __forceinline__ void split1(float v, unsigned short& h, unsigned short& l) {
    __nv_bfloat16 hb = __float2bfloat16(v);
    __nv_bfloat16 lb = __float2bfloat16(v - __bfloat162float(hb));
    h = __bfloat16_as_ushort(hb);
    l = __bfloat16_as_ushort(lb);
}

// ================= pre-split bf16 HMMA GEMM (exact R5 structure) =============
// C[M,Ntot] = relu(A@B^T + bias); A,B pre-split bf16 hi/lo, K padded.
// 3 passes: hi*hi + hi*lo + lo*hi, fp32 accumulators.
// 2-stage cp.async ring, 2 CTAs/SM, B fragments via ldsm2 (x4-for-B is a
// measured 1.6x regression — do not "optimize" it back in).
template <int BF16OUT>
__global__ void __launch_bounds__(256, 2)
mma_gemm(const unsigned short* __restrict__ Ahi, const unsigned short* __restrict__ Alo,
         const unsigned short* __restrict__ Bhi, const unsigned short* __restrict__ Blo,
         const float* __restrict__ bias, float* __restrict__ Cf,
         unsigned short* __restrict__ Chi, unsigned short* __restrict__ Clo,
         int M, int Kp, int Ntot) {
    constexpr int BM = 128, BN = 128, BK = 32;
    constexpr int LDB = 80;                 // 64B data + 16B pad (LDSM conflict-free)
    constexpr int TILE = BM * LDB;          // 10240
    constexpr int STAGE = 4 * TILE;         // Ahi,Alo,Bhi,Blo

    extern __shared__ char sm[];
    const int tid = threadIdx.x, lane = tid & 31, wid = tid >> 5;
    const int bm = blockIdx.y * BM, bn = blockIdx.x * BN;
    const int wm = (wid >> 2) * 64, wn = (wid & 3) * 32;
    const uint32_t sb = smem_u32(sm);
    const int nk = Kp / BK;

    const int lr = tid >> 2;
    const int lcB = (tid & 3) * 16;
    const int lcE = (tid & 3) * 8;

    auto load_stage = [&](int i, int s) {
        const long k0 = (long)i * BK;
        const uint32_t base = sb + s * STAGE;
#pragma unroll
        for (int rep = 0; rep < 2; rep++) {
            const int r = lr + rep * 64;
            const uint32_t doff = (uint32_t)(r * LDB) + lcB;
            const int arow = (bm + r < M) ? (bm + r) : (M - 1);
            const int aok = (bm + r < M) ? 16 : 0;
            const long aoff = (long)arow * Kp + k0 + lcE;
            const long boff = (long)(bn + r) * Kp + k0 + lcE;
            cpa16(base + doff,            Ahi + aoff, aok);
            cpa16(base + TILE + doff,     Alo + aoff, aok);
            cpa16(base + 2 * TILE + doff, Bhi + boff, 16);
            cpa16(base + 3 * TILE + doff, Blo + boff, 16);
        }
        CP_COMMIT();
    };

    float acc[4][4][4];
#pragma unroll
    for (int i = 0; i < 4; i++)
#pragma unroll
        for (int j = 0; j < 4; j++)
#pragma unroll
            for (int v = 0; v < 4; v++) acc[i][j][v] = 0.f;

    const int a_row  = (lane & 7) + ((lane >> 3) & 1) * 8;
    const int a_kadd = (lane >> 4) * 8;
    const int b_row  = lane & 7;
    const int b_kadd = ((lane >> 3) & 1) * 8;

    load_stage(0, 0);
    load_stage(1, 1);

#pragma unroll 1
    for (int i = 0; i < nk; i++) {
        const int cur = i & 1;
        CP_WAIT1();                  // stage `cur` (group i) complete
        __syncthreads();

        const uint32_t abase = sb + cur * STAGE;
        const uint32_t bbase = abase + 2 * TILE;
#pragma unroll
        for (int ks = 0; ks < 2; ks++) {
            const int k16 = ks * 16;
            uint32_t ahi[4][4], alo[4][4], bhi[4][2], blo[4][2];
#pragma unroll
            for (int mi = 0; mi < 4; mi++) {
                uint32_t ad = abase + (uint32_t)((wm + mi * 16 + a_row) * LDB + (k16 + a_kadd) * 2);
                ldsm4(ahi[mi], ad);
                ldsm4(alo[mi], ad + TILE);
            }
#pragma unroll
            for (int ni = 0; ni < 4; ni++) {
                uint32_t bd = bbase + (uint32_t)((wn + ni * 8 + b_row) * LDB + (k16 + b_kadd) * 2);
                ldsm2(bhi[ni], bd);
                ldsm2(blo[ni], bd + TILE);
            }
#pragma unroll
            for (int mi = 0; mi < 4; mi++)
#pragma unroll
                for (int ni = 0; ni < 4; ni++) mma16816(acc[mi][ni], ahi[mi], bhi[ni]);
#pragma unroll
            for (int mi = 0; mi < 4; mi++)
#pragma unroll
                for (int ni = 0; ni < 4; ni++) mma16816(acc[mi][ni], ahi[mi], blo[ni]);
#pragma unroll
            for (int mi = 0; mi < 4; mi++)
#pragma unroll
                for (int ni = 0; ni < 4; ni++) mma16816(acc[mi][ni], alo[mi], bhi[ni]);
        }
        __syncthreads();             // all warps done reading stage `cur`
        if (i + 2 < nk) load_stage(i + 2, cur);
    }

    // epilogue: bias + relu; fp32 out or bf16 hi/lo split out
#pragma unroll
    for (int mi = 0; mi < 4; mi++) {
#pragma unroll
        for (int ni = 0; ni < 4; ni++) {
            const int col = bn + wn + ni * 8 + (lane & 3) * 2;
            const float b0 = bias[col], b1 = bias[col + 1];
#pragma unroll
            for (int half = 0; half < 2; half++) {
                const int r = bm + wm + mi * 16 + (lane >> 2) + half * 8;
                if (r >= M) continue;
                float v0 = fmaxf(acc[mi][ni][half * 2 + 0] + b0, 0.f);
                float v1 = fmaxf(acc[mi][ni][half * 2 + 1] + b1, 0.f);
                if (BF16OUT) {
                    unsigned short h0, l0, h1, l1;
                    split1(v0, h0, l0);
                    split1(v1, h1, l1);
                    *(uint32_t*)(Chi + (long)r * Ntot + col) = (uint32_t)h0 | ((uint32_t)h1 << 16);
                    *(uint32_t*)(Clo + (long)r * Ntot + col) = (uint32_t)l0 | ((uint32_t)l1 << 16);
                } else {
                    float2 o = make_float2(v0, v1);
                    *(float2*)(Cf + (long)r * Ntot + col) = o;
                }
            }
        }
    }
}

// ---------------- split x: fp32 [M,K] -> bf16 hi/lo [M,Kp] ----------------
__global__ void split_pad(const float* __restrict__ in, unsigned short* __restrict__ hi,
                          unsigned short* __restrict__ lo, int M, int K, int Kp) {
    long idx = (long)blockIdx.x * blockDim.x + threadIdx.x;
    long tot = (long)M * (Kp / 4);
    if (idx >= tot) return;
    int r = (int)(idx / (Kp / 4));
    int c = (int)(idx % (Kp / 4)) * 4;
    float4 v = make_float4(0.f, 0.f, 0.f, 0.f);
    if (c < K) v = *(const float4*)(in + (long)r * K + c);
    unsigned short h[4], l[4];
    split1(v.x, h[0], l[0]); split1(v.y, h[1], l[1]);
    split1(v.z, h[2], l[2]); split1(v.w, h[3], l[3]);
    *(ushort4*)(hi + (long)r * Kp + c) = make_ushort4(h[0], h[1], h[2], h[3]);
    *(ushort4*)(lo + (long)r * Kp + c) = make_ushort4(l[0], l[1], l[2], l[3]);
}

// ---------------- transpose + split: W[R,C] -> hi/lo[C,Rp] ----------------
__global__ void transpose_split(const float* __restrict__ in, unsigned short* __restrict__ hi,
                                unsigned short* __restrict__ lo, int R, int C, int Rp) {
    __shared__ float t[32][33];
    int c = blockIdx.x * 32 + threadIdx.x;
    int r = blockIdx.y * 32 + threadIdx.y;
#pragma unroll
    for (int i = 0; i < 32; i += 8)
        t[threadIdx.y + i][threadIdx.x] = (r + i < R && c < C) ? in[(long)(r + i) * C + c] : 0.f;
    __syncthreads();
    int oc  = blockIdx.y * 32 + threadIdx.x;
    int orr = blockIdx.x * 32 + threadIdx.y;
#pragma unroll
    for (int i = 0; i < 32; i += 8)
        if (orr + i < C && oc < Rp) {
            float v = t[threadIdx.x][threadIdx.y + i];
            unsigned short h, l;
            split1(v, h, l);
            hi[(long)(orr + i) * Rp + oc] = h;
            lo[(long)(orr + i) * Rp + oc] = l;
        }
}

// ---------------- small GEMM: h = fe(Nx128) @ W(128x32) ----------------
__global__ void gemm_z_g1(const float* __restrict__ A, const float* __restrict__ W,
                          float* __restrict__ C, int M) {
    __shared__ float Ws[ZD * G1D];
    __shared__ float Asm[8 * ZD];
    const int t = threadIdx.x;
    const int base = blockIdx.x * 8;
#pragma unroll
    for (int i = 0; i < 16; i++) Ws[t + i * 256] = W[t + i * 256];
#pragma unroll
    for (int i = 0; i < 4; i++) {
        int idx = t + i * 256;
        int r = idx >> 7, c = idx & 127;
        Asm[r * ZD + c] = (base + r < M) ? A[(long)(base + r) * ZD + c] : 0.f;
    }
    __syncthreads();
    int r = t >> 5, c = t & 31;
    if (base + r < M) {
        float s = 0.f;
#pragma unroll
        for (int k = 0; k < ZD; k++) s = fmaf(Asm[r * ZD + k], Ws[k * G1D + c], s);
        C[(long)(base + r) * G1D + c] = s;
    }
}

// ---------------- head GEMMs ----------------
__global__ void gemm_heads(const float* __restrict__ H, const float* __restrict__ W2,
                           const float* __restrict__ W3,
                           float* __restrict__ HM, float* __restrict__ HL, int M) {
    __shared__ float sh[256 * 33];
    __shared__ float W2s[G1D * OUTD], W3s[G1D * OUTD];
    const int t = threadIdx.x;
    const int base = blockIdx.x * 256;
    if (t < G1D * OUTD) { W2s[t] = W2[t]; W3s[t] = W3[t]; }
#pragma unroll
    for (int i = 0; i < 32; i++) {
        int idx = t + i * 256;
        int r = idx >> 5, c = idx & 31;
        sh[r * 33 + c] = (base + r < M) ? H[(long)(base + r) * G1D + c] : 0.f;
    }
    __syncthreads();
    int row = base + t;
    if (row < M) {
        float m0 = 0, m1 = 0, m2 = 0, l0 = 0, l1 = 0, l2 = 0;
#pragma unroll
        for (int k = 0; k < G1D; k++) {
            float v = sh[t * 33 + k];
            m0 = fmaf(v, W2s[k * 3 + 0], m0);
            m1 = fmaf(v, W2s[k * 3 + 1], m1);
            m2 = fmaf(v, W2s[k * 3 + 2], m2);
            l0 = fmaf(v, W3s[k * 3 + 0], l0);
            l1 = fmaf(v, W3s[k * 3 + 1], l1);
            l2 = fmaf(v, W3s[k * 3 + 2], l2);
        }
        HM[row * 3 + 0] = m0; HM[row * 3 + 1] = m1; HM[row * 3 + 2] = m2;
        HL[row * 3 + 0] = l0; HL[row * 3 + 1] = l1; HL[row * 3 + 2] = l2;
    }
}

// ---------------- graph helpers ----------------
__global__ void init_deg_kernel(float* deg, int n) {
    int i = blockIdx.x * blockDim.x + threadIdx.x;
    if (i < n) deg[i] = 1.0f;
}
__global__ void deg_kernel(const int* __restrict__ dst, float* deg, int E) {
    int e = blockIdx.x * blockDim.x + threadIdx.x;
    if (e < E) atomicAdd(&deg[dst[e]], 1.0f);
}
__global__ void dinv_kernel(const float* __restrict__ deg, float* dinv, int n) {
    int i = blockIdx.x * blockDim.x + threadIdx.x;
    if (i < n) dinv[i] = rsqrtf(deg[i]);
}
// 8 threads per edge, float4 per thread: index loads /4, LDG /4, REDs unchanged
__global__ void agg1_kernel(const int* __restrict__ src, const int* __restrict__ dst,
                            const float* __restrict__ dinv, const float* __restrict__ H,
                            float* __restrict__ AGG, int E) {
    long tid = (long)blockIdx.x * blockDim.x + threadIdx.x;
    if (tid >= (long)E * 8) return;
    int e = (int)(tid >> 3), j = (int)(tid & 7) * 4;
    int s = src[e], d = dst[e];
    float w = dinv[s] * dinv[d];
    float4 hv = *(const float4*)(H + (long)s * G1D + j);
    float* dstp = AGG + (long)d * G1D + j;
    atomicAdd(dstp + 0, hv.x * w);
    atomicAdd(dstp + 1, hv.y * w);
    atomicAdd(dstp + 2, hv.z * w);
    atomicAdd(dstp + 3, hv.w * w);
}
__global__ void h1_kernel(const float* __restrict__ AGG, const float* __restrict__ H,
                          const float* __restrict__ dinv, float* __restrict__ H1, int n) {
    long tid = (long)blockIdx.x * blockDim.x + threadIdx.x;
    if (tid >= (long)n * G1D) return;
    int i = (int)(tid >> 5);
    float w = dinv[i];
    H1[tid] = tanhf(AGG[tid] + H[tid] * w * w);
}
__global__ void agg2_kernel(const int* __restrict__ src, const int* __restrict__ dst,
                            const float* __restrict__ dinv,
                            const float* __restrict__ HM, const float* __restrict__ HL,
                            float* __restrict__ AM, float* __restrict__ AL, int E) {
    int e = blockIdx.x * blockDim.x + threadIdx.x;
    if (e >= E) return;
    int s = src[e], d = dst[e];
    float w = dinv[s] * dinv[d];
#pragma unroll
    for (int j = 0; j < OUTD; j++) {
        atomicAdd(&AM[d * OUTD + j], HM[s * OUTD + j] * w);
        atomicAdd(&AL[d * OUTD + j], HL[s * OUTD + j] * w);
    }
}
__global__ void fin_kernel(const float* __restrict__ AM, const float* __restrict__ AL,
                           const float* __restrict__ HM, const float* __restrict__ HL,
                           const float* __restrict__ dinv, float* __restrict__ out, int n) {
    int tid = blockIdx.x * blockDim.x + threadIdx.x;
    if (tid >= n * OUTD) return;
    int i = tid / OUTD;
    float w = dinv[i] * dinv[i];
    out[tid]            = AM[tid] + HM[tid] * w;
    out[n * OUTD + tid] = AL[tid] + HL[tid] * w;
}
__global__ void pe_kernel(const float* __restrict__ fe, const float* __restrict__ coords,
                          float* __restrict__ out, int n) {
    long tid = (long)blockIdx.x * blockDim.x + threadIdx.x;
    if (tid >= (long)n * ZD) return;
    int node = (int)(tid >> 7);
    int z = (int)(tid & 127);
    int c = z >> 6;
    int t = z & 63;
    int idx = (t < 32) ? t : t - 32;
    float fr = exp2f(6.0f * (1.0f - (float)idx * (1.0f / 31.0f)));
    float v = coords[node * 2 + c] * fr;
    float p = (t < 32) ? sinf(v) : cosf(v);
    out[tid] = fe[tid] + 0.1f * p;
}

// ---------------- launch ----------------
extern "C" void kernel_launch(void* const* d_in, const int* in_sizes, int n_in,
                              void* d_out, int out_size) {
    const float* x      = (const float*)d_in[0];
    const float* coords = (const float*)d_in[1];
    const float* W1     = (const float*)d_in[2];
    const float* b1     = (const float*)d_in[3];
    const float* W2     = (const float*)d_in[4];
    const float* b2     = (const float*)d_in[5];
    const float* Wg1    = (const float*)d_in[6];
    const float* Wg2    = (const float*)d_in[7];
    const float* Wg3    = (const float*)d_in[8];
    const int*   ei     = (const int*)d_in[9];
    const int E = in_sizes[9] / 2;
    const int* src = ei;
    const int* dst = ei + E;
    float* out = (float*)d_out;

    unsigned short *xhi, *xlo, *w1hi, *w1lo, *w2hi, *w2lo, *f1hi, *f1lo;
    float *fe, *deg, *dinv, *h, *agg1, *h1, *hm, *hl, *am, *al;
    cudaGetSymbolAddress((void**)&xhi,  g_xhi);
    cudaGetSymbolAddress((void**)&xlo,  g_xlo);
    cudaGetSymbolAddress((void**)&w1hi, g_w1hi);
    cudaGetSymbolAddress((void**)&w1lo, g_w1lo);
    cudaGetSymbolAddress((void**)&w2hi, g_w2hi);
    cudaGetSymbolAddress((void**)&w2lo, g_w2lo);
    cudaGetSymbolAddress((void**)&f1hi, g_f1hi);
    cudaGetSymbolAddress((void**)&f1lo, g_f1lo);
    cudaGetSymbolAddress((void**)&fe,   g_fe);
    cudaGetSymbolAddress((void**)&deg,  g_deg);
    cudaGetSymbolAddress((void**)&dinv, g_dinv);
    cudaGetSymbolAddress((void**)&h,    g_h);
    cudaGetSymbolAddress((void**)&agg1, g_agg1);
    cudaGetSymbolAddress((void**)&h1,   g_h1);
    cudaGetSymbolAddress((void**)&hm,   g_hm);
    cudaGetSymbolAddress((void**)&hl,   g_hl);
    cudaGetSymbolAddress((void**)&am,   g_aggm);
    cudaGetSymbolAddress((void**)&al,   g_aggl);

    constexpr int SMEM = 2 * 4 * 128 * 80;   // 81920 B (2-stage ring, 2 CTAs/SM)
    cudaFuncSetAttribute(mma_gemm<0>, cudaFuncAttributeMaxDynamicSharedMemorySize, SMEM);
    cudaFuncSetAttribute(mma_gemm<1>, cudaFuncAttributeMaxDynamicSharedMemorySize, SMEM);

    // launches 1-3: accumulator zeroing (graph replays)
    cudaMemsetAsync(agg1, 0, sizeof(float) * NN * G1D);
    cudaMemsetAsync(am,   0, sizeof(float) * NN * OUTD);
    cudaMemsetAsync(al,   0, sizeof(float) * NN * OUTD);

    // launches 4-6: operand pre-split
    split_pad<<<(int)(((long)NN * (KP1 / 4) + 255) / 256), 256>>>(x, xhi, xlo, NN, FF, KP1);
    {
        dim3 b(32, 8);
        transpose_split<<<dim3((H1D + 31) / 32, (KP1 + 31) / 32), b>>>(W1, w1hi, w1lo, FF, H1D, KP1);
        transpose_split<<<dim3((ZD + 31) / 32, (H1D + 31) / 32), b>>>(W2, w2hi, w2lo, H1D, ZD, H1D);
    }

    // launch 7 (ncu -s picks this one): big GEMM
    mma_gemm<1><<<dim3(H1D / 128, (NN + 127) / 128), 256, SMEM>>>(
        xhi, xlo, w1hi, w1lo, b1, nullptr, f1hi, f1lo, NN, KP1, H1D);
    mma_gemm<0><<<dim3(ZD / 128, (NN + 127) / 128), 256, SMEM>>>(
        f1hi, f1lo, w2hi, w2lo, b2, fe, nullptr, nullptr, NN, H1D, ZD);

    // positional embedding (mu | logstd | po_emb)
    pe_kernel<<<(int)(((long)NN * ZD + 255) / 256), 256>>>(fe, coords, out + 2 * NN * OUTD, NN);

    // GCN layer 1
    gemm_z_g1<<<(NN + 7) / 8, 256>>>(fe, Wg1, h, NN);
    init_deg_kernel<<<(NN + 255) / 256, 256>>>(deg, NN);
    deg_kernel<<<(E + 255) / 256, 256>>>(dst, deg, E);
    dinv_kernel<<<(NN + 255) / 256, 256>>>(deg, dinv, NN);
    agg1_kernel<<<(int)(((long)E * 8 + 255) / 256), 256>>>(src, dst, dinv, h, agg1, E);
    h1_kernel<<<(int)(((long)NN * G1D + 255) / 256), 256>>>(agg1, h, dinv, h1, NN);

    // heads
    gemm_heads<<<(NN + 255) / 256, 256>>>(h1, Wg2, Wg3, hm, hl, NN);
    agg2_kernel<<<(E + 255) / 256, 256>>>(src, dst, dinv, hm, hl, am, al, E);
    fin_kernel<<<(NN * OUTD + 255) / 256, 256>>>(am, al, hm, hl, dinv, out, NN);
}